// round 1
// baseline (speedup 1.0000x reference)
#include <cuda_runtime.h>
#include <math.h>

// Problem constants (fixed by setup_inputs / reference)
#define MPI_HH 300
#define MPI_WW 400
#define MPI_DD 24
#define GRID_H 4
#define GRID_W 6
#define ATL_C 16
#define ATL_H 1200
#define ATL_W 2400
#define IMG_H 240
#define IMG_W 320
#define NPIX (IMG_H * IMG_W)
#define NEAR_D 2.0f
#define FAR_D 100.0f
// cx_mpi = 160 + (400-320)/2 ; cy_mpi = 120 + (300-240)/2
#define CX_MPI 200.0f
#define CY_MPI 150.0f
#define REF_F 300.0f

#define HID 48
#define FEAT_C 16
#define VEMB_N 27
#define W1T_STRIDE 44  // 43 in-dims padded to 44 (float4-aligned rows)

__global__ __launch_bounds__(128)
void mpi_render_kernel(const float* __restrict__ extrin,
                       const float* __restrict__ intrin,
                       const float* __restrict__ atlas,
                       const float* __restrict__ w1,
                       const float* __restrict__ b1,
                       const float* __restrict__ w2,
                       const float* __restrict__ b2,
                       float* __restrict__ out)
{
    // Shared: w1 transposed to [j][i] with padded stride so per-hidden-unit rows
    // are contiguous & float4 loadable (broadcast LDS.128, conflict-free).
    __shared__ float  w1t[HID * W1T_STRIDE];
    __shared__ float4 w2s[HID];
    __shared__ float  b1s[HID];
    __shared__ float  b2s[4];

    const int tid = threadIdx.x;
    for (int idx = tid; idx < HID * W1T_STRIDE; idx += blockDim.x) {
        int j = idx / W1T_STRIDE;
        int i = idx - j * W1T_STRIDE;
        w1t[idx] = (i < 43) ? w1[i * HID + j] : 0.0f;
    }
    if (tid < HID) {
        w2s[tid] = make_float4(w2[tid * 4 + 0], w2[tid * 4 + 1],
                               w2[tid * 4 + 2], w2[tid * 4 + 3]);
        b1s[tid] = b1[tid];
    }
    if (tid < 4) b2s[tid] = b2[tid];
    __syncthreads();

    const int pix = blockIdx.x * blockDim.x + tid;
    if (pix >= NPIX) return;
    const int yi = pix / IMG_W;
    const int xi = pix - yi * IMG_W;

    // ---------------- Per-pixel geometry ----------------
    // E = extrin[0] (4x4 row-major), R = E[:3,:3], T = E[:3,3]
    const float R00 = extrin[0],  R01 = extrin[1],  R02 = extrin[2],  T0 = extrin[3];
    const float R10 = extrin[4],  R11 = extrin[5],  R12 = extrin[6],  T1 = extrin[7];
    const float R20 = extrin[8],  R21 = extrin[9],  R22 = extrin[10], T2 = extrin[11];

    // cam_o = -R^T T
    const float cox = -(R00 * T0 + R10 * T1 + R20 * T2);
    const float coy = -(R01 * T0 + R11 * T1 + R21 * T2);
    const float coz = -(R02 * T0 + R12 * T1 + R22 * T2);

    // General 3x3 inverse of K (matches jnp.linalg.inv within fp32 noise)
    const float ka = intrin[0], kb = intrin[1], kc = intrin[2];
    const float kd = intrin[3], ke = intrin[4], kf = intrin[5];
    const float kg = intrin[6], kh = intrin[7], ki = intrin[8];
    const float det = ka * (ke * ki - kf * kh)
                    - kb * (kd * ki - kf * kg)
                    + kc * (kd * kh - ke * kg);
    const float idet = 1.0f / det;
    const float i00 = (ke * ki - kf * kh) * idet;
    const float i01 = (kc * kh - kb * ki) * idet;
    const float i02 = (kb * kf - kc * ke) * idet;
    const float i10 = (kf * kg - kd * ki) * idet;
    const float i11 = (ka * ki - kc * kg) * idet;
    const float i12 = (kc * kd - ka * kf) * idet;
    const float i20 = (kd * kh - ke * kg) * idet;
    const float i21 = (kb * kg - ka * kh) * idet;
    const float i22 = (ka * ke - kb * kd) * idet;

    const float pxf = (float)xi;
    const float pyf = (float)yi;
    const float dc0 = i00 * pxf + i01 * pyf + i02;
    const float dc1 = i10 * pxf + i11 * pyf + i12;
    const float dc2 = i20 * pxf + i21 * pyf + i22;

    // dir_w[i] = sum_j R[j][i] * dir_cam[j]   (R^T * dir_cam)
    const float dwx = R00 * dc0 + R10 * dc1 + R20 * dc2;
    const float dwy = R01 * dc0 + R11 * dc1 + R21 * dc2;
    const float dwz = R02 * dc0 + R12 * dc1 + R22 * dc2;

    const float invn = 1.0f / sqrtf(dwx * dwx + dwy * dwy + dwz * dwz);
    const float vx = dwx * invn, vy = dwy * invn, vz = dwz * invn;

    // View embedding: [v, sin(v*1), cos(v*1), sin(v*2), cos(v*2), sin(v*4), cos(v*4), sin(v*8), cos(v*8)]
    float vemb[28];
    vemb[0] = vx; vemb[1] = vy; vemb[2] = vz;
    #pragma unroll
    for (int kk = 0; kk < 4; kk++) {
        const float sc = (float)(1 << kk);
        vemb[3 + 6 * kk + 0] = sinf(vx * sc);
        vemb[3 + 6 * kk + 1] = sinf(vy * sc);
        vemb[3 + 6 * kk + 2] = sinf(vz * sc);
        vemb[3 + 6 * kk + 3] = cosf(vx * sc);
        vemb[3 + 6 * kk + 4] = cosf(vy * sc);
        vemb[3 + 6 * kk + 5] = cosf(vz * sc);
    }
    vemb[27] = 0.0f;  // pad (pairs with zero weight column)

    // Per-pixel partial layer-1: g[j] = b1[j] + vemb . w1[16:43, j]
    float g[HID];
    #pragma unroll
    for (int j = 0; j < HID; j++) {
        const float4* wp = (const float4*)(w1t + j * W1T_STRIDE + 16);
        float acc = b1s[j];
        #pragma unroll
        for (int q = 0; q < 7; q++) {
            const float4 wv = wp[q];
            acc += wv.x * vemb[4 * q + 0] + wv.y * vemb[4 * q + 1]
                 + wv.z * vemb[4 * q + 2] + wv.w * vemb[4 * q + 3];
        }
        g[j] = acc;
    }

    // ---------------- Plane loop (front-to-back: k = 23 .. 0) ----------------
    const float inv_near = 1.0f / NEAR_D;
    const float inv_far  = 1.0f / FAR_D;
    const float dstep = (inv_far - inv_near) / (float)(MPI_DD - 1);
    const float invdz = 1.0f / dwz;
    const float bb0 = b2s[0], bb1 = b2s[1], bb2 = b2s[2], bb3 = b2s[3];

    float Tt = 1.0f;
    float orr = 0.0f, ogg = 0.0f, obb = 0.0f;

    #pragma unroll 1
    for (int k = MPI_DD - 1; k >= 0; --k) {
        const float depth = 1.0f / (inv_near + (float)(MPI_DD - 1 - k) * dstep);
        const float t = (depth - coz) * invdz;
        const float pz = coz + t * dwz;
        const float ipz = 1.0f / pz;
        const float pxv = (cox + t * dwx) * ipz * REF_F + CX_MPI;
        const float pyv = (coy + t * dwy) * ipz * REF_F + CY_MPI;

        const bool valid = (t > 0.0f)
                        && (pxv >= 0.0f) && (pxv <= (float)(MPI_WW - 1))
                        && (pyv >= 0.0f) && (pyv <= (float)(MPI_HH - 1));
        if (!valid) continue;  // alpha forced to 0 -> no contribution, T unchanged

        const int colk = k % GRID_W;
        const int rowk = k / GRID_W;
        const float ax = ((float)colk + pxv / (float)(MPI_WW - 1)) * ((float)(ATL_W - 1) / (float)GRID_W);
        const float ay = ((float)rowk + pyv / (float)(MPI_HH - 1)) * ((float)(ATL_H - 1) / (float)GRID_H);

        const float fx0 = floorf(ax);
        const float fy0 = floorf(ay);
        int x0 = (int)fx0;
        int y0 = (int)fy0;
        const int x1 = min(x0 + 1, ATL_W - 1);
        const int y1 = min(y0 + 1, ATL_H - 1);
        const float wx = ax - fx0;
        const float wy = ay - fy0;

        const int o00 = y0 * ATL_W + x0;
        const int o01 = y0 * ATL_W + x1;
        const int o10 = y1 * ATL_W + x0;
        const int o11 = y1 * ATL_W + x1;

        float feat[FEAT_C];
        #pragma unroll
        for (int cc = 0; cc < FEAT_C; cc++) {
            const float* p = atlas + cc * (ATL_H * ATL_W);
            const float a00 = __ldg(p + o00);
            const float a01 = __ldg(p + o01);
            const float a10 = __ldg(p + o10);
            const float a11 = __ldg(p + o11);
            const float top = fmaf(wx, a01 - a00, a00);
            const float bot = fmaf(wx, a11 - a10, a10);
            feat[cc] = fmaf(wy, bot - top, top);
        }

        float s0 = bb0, s1 = bb1, s2 = bb2, s3 = bb3;
        #pragma unroll
        for (int j = 0; j < HID; j++) {
            const float4* wp = (const float4*)(w1t + j * W1T_STRIDE);
            float hj = g[j];
            float4 wv;
            wv = wp[0]; hj += wv.x * feat[0]  + wv.y * feat[1]  + wv.z * feat[2]  + wv.w * feat[3];
            wv = wp[1]; hj += wv.x * feat[4]  + wv.y * feat[5]  + wv.z * feat[6]  + wv.w * feat[7];
            wv = wp[2]; hj += wv.x * feat[8]  + wv.y * feat[9]  + wv.z * feat[10] + wv.w * feat[11];
            wv = wp[3]; hj += wv.x * feat[12] + wv.y * feat[13] + wv.z * feat[14] + wv.w * feat[15];
            hj = fmaxf(hj, 0.0f);
            const float4 w2v = w2s[j];
            s0 = fmaf(hj, w2v.x, s0);
            s1 = fmaf(hj, w2v.y, s1);
            s2 = fmaf(hj, w2v.z, s2);
            s3 = fmaf(hj, w2v.w, s3);
        }

        const float cr = 1.0f / (1.0f + __expf(-s0));
        const float cg = 1.0f / (1.0f + __expf(-s1));
        const float cb = 1.0f / (1.0f + __expf(-s2));
        const float al = 1.0f / (1.0f + __expf(-s3));

        const float wgt = al * Tt;
        orr = fmaf(cr, wgt, orr);
        ogg = fmaf(cg, wgt, ogg);
        obb = fmaf(cb, wgt, obb);
        Tt *= (1.0f - al);
    }

    out[pix * 3 + 0] = orr;
    out[pix * 3 + 1] = ogg;
    out[pix * 3 + 2] = obb;
}

extern "C" void kernel_launch(void* const* d_in, const int* in_sizes, int n_in,
                              void* d_out, int out_size)
{
    // Identify inputs by element count (robust to scalar H/W placement):
    // extrin=16, intrin=9, atlas=46,080,000, w1=2064, b1=48, w2=192, b2=4
    const float* extrin = nullptr;
    const float* intrin = nullptr;
    const float* atlas  = nullptr;
    const float* w1 = nullptr;
    const float* b1 = nullptr;
    const float* w2 = nullptr;
    const float* b2 = nullptr;
    for (int i = 0; i < n_in; i++) {
        switch (in_sizes[i]) {
            case 16:        extrin = (const float*)d_in[i]; break;
            case 9:         intrin = (const float*)d_in[i]; break;
            case ATL_C * ATL_H * ATL_W: atlas = (const float*)d_in[i]; break;
            case 43 * HID:  w1 = (const float*)d_in[i]; break;
            case HID:       b1 = (const float*)d_in[i]; break;
            case HID * 4:   w2 = (const float*)d_in[i]; break;
            case 4:         b2 = (const float*)d_in[i]; break;
            default: break; // H, W scalars ignored (fixed 240x320)
        }
    }
    float* out = (float*)d_out;
    const int threads = 128;
    const int grid = (NPIX + threads - 1) / threads;
    mpi_render_kernel<<<grid, threads>>>(extrin, intrin, atlas, w1, b1, w2, b2, out);
}